// round 10
// baseline (speedup 1.0000x reference)
#include <cuda_runtime.h>
#include <cuda_bf16.h>
#include <stdint.h>

// Problem constants
#define Bb 128
#define Dd 128
#define Tt 2048
#define Cc 64
#define NTOT (Bb*Tt)            // 262144 rows

// K1 config: one block per batch row b
#define G1   128
#define TH1  512
#define JS   64                 // t-columns per stage
#define NST  (Tt/JS)            // 32 stages
#define SW   36                 // bf16-tile row stride in 32-bit words (32 data + 4 pad)
#define TILEW (Dd*SW)           // 4608 words per tile

// Static device scratch (no allocations allowed)
__device__ float g_partial[(size_t)G1 * Cc * Dd];   // 4 MB per-block partials
__device__ int   g_pcnt[Cc * G1];                   // [c][g]
__device__ float g_psq[G1];
__device__ float g_sumsq;
__device__ float g_lpart[Cc];

// ---------------------------------------------------------------------------
__device__ __forceinline__ uint32_t oh2(int L0, int L1, int r) {
    // packed bf16x2 one-hot: low half = (L0==r), high half = (L1==r)
    return ((L0 == r) ? 0x3F80u : 0u) | ((L1 == r) ? 0x3F800000u : 0u);
}
__device__ __forceinline__ void mma16816(float* c, const uint32_t* a,
                                         uint32_t b0, uint32_t b1) {
    asm volatile(
        "mma.sync.aligned.m16n8k16.row.col.f32.bf16.bf16.f32 "
        "{%0,%1,%2,%3}, {%4,%5,%6,%7}, {%8,%9}, {%0,%1,%2,%3};"
        : "+f"(c[0]), "+f"(c[1]), "+f"(c[2]), "+f"(c[3])
        : "r"(a[0]), "r"(a[1]), "r"(a[2]), "r"(a[3]), "r"(b0), "r"(b1));
}

// ---------------------------------------------------------------------------
// K1: one-hot GEMM via mma.sync (HMMA bf16, hi/lo split), C in registers.
// D[c][d] += onehot[c][t] * (feat_hi + feat_lo)[d][t], per-block over t.
// ---------------------------------------------------------------------------
__global__ void __launch_bounds__(TH1, 1)
k1_main(const float* __restrict__ feature, const int* __restrict__ lab32) {
    extern __shared__ float sm[];
    uint32_t* tileH = (uint32_t*)sm;               // 4608 words
    uint32_t* tileL = tileH + TILEW;               // 4608 words
    int*   labs = (int*)(tileL + TILEW);           // 2048 ints
    int*   cnt  = labs + Tt;                       // 64
    float* red  = (float*)(cnt + Cc);              // 16
    int*   sflag= (int*)(red + 16);                // 1

    const int tid = threadIdx.x;
    const int w = tid >> 5;
    const int l = tid & 31;
    const int b = blockIdx.x;

    if (tid < Cc) cnt[tid] = 0;
    if (tid == 0) *sflag = 0;
    __syncthreads();

    // Label-width probe: odd words of the FIRST 4096 int64 slots (word idx
    // < 8192, in-bounds for both widths; values < 64 => genuine int64 buffer
    // has all-zero odd words).
    {
        int any = 0;
        #pragma unroll
        for (int k = 0; k < 4096 / TH1; ++k)
            any |= lab32[(tid + k * TH1) * 2 + 1];
        #pragma unroll
        for (int o = 16; o > 0; o >>= 1) any |= __shfl_xor_sync(0xffffffff, any, o);
        if (l == 0 && any) atomicOr(sflag, 1);
    }
    __syncthreads();
    const int is64 = (*sflag == 0) ? 1 : 0;

    // preload this block's 2048 labels + histogram
    {
        const int base = b * Tt;
        #pragma unroll
        for (int k = 0; k < Tt / TH1; ++k) {
            int i = tid + k * TH1;
            int lab = is64 ? lab32[(base + i) * 2] : lab32[base + i];
            labs[i] = lab;
            atomicAdd(&cnt[lab], 1);
        }
    }
    __syncthreads();

    // ---- mappings ----
    const float* fb = feature + (size_t)b * Dd * Tt;
    const int d0 = tid >> 4;                       // convert: base row 0..31
    const int j0 = (tid & 15) * 4;                 // convert: t offset (float4)
    const float* bg = fb + (size_t)d0 * Tt + j0;

    const int mbase = (w & 1) * 32;                // warp's class half
    const int dbase = (w >> 1) * 16;               // warp's d range (16 wide)
    const int q2    = (l & 3) * 2;                 // fragment k-pair column
    const int rowa  = l >> 2;                      // fragment row (0..7)

    float C[2][2][4];
    #pragma unroll
    for (int mi = 0; mi < 2; ++mi)
        #pragma unroll
        for (int ni = 0; ni < 2; ++ni)
            #pragma unroll
            for (int q = 0; q < 4; ++q) C[mi][ni][q] = 0.0f;

    float sq = 0.0f;
    float4 R[4];
    #pragma unroll
    for (int k = 0; k < 4; ++k)
        R[k] = *reinterpret_cast<const float4*>(bg + (size_t)k * 32 * Tt);

    for (int s = 0; s < NST; ++s) {
        // ---- convert fp32 -> bf16 hi/lo into tiles (+ sumsq) ----
        #pragma unroll
        for (int k = 0; k < 4; ++k) {
            float4 v = R[k];
            sq += v.x * v.x + v.y * v.y + v.z * v.z + v.w * v.w;
            __nv_bfloat16 hx = __float2bfloat16_rn(v.x), hy = __float2bfloat16_rn(v.y);
            __nv_bfloat16 hz = __float2bfloat16_rn(v.z), hw = __float2bfloat16_rn(v.w);
            __nv_bfloat16 lx = __float2bfloat16_rn(v.x - __bfloat162float(hx));
            __nv_bfloat16 ly = __float2bfloat16_rn(v.y - __bfloat162float(hy));
            __nv_bfloat16 lz = __float2bfloat16_rn(v.z - __bfloat162float(hz));
            __nv_bfloat16 lw = __float2bfloat16_rn(v.w - __bfloat162float(hw));
            uint32_t h0 = ((uint32_t)__bfloat16_as_ushort(hy) << 16) | __bfloat16_as_ushort(hx);
            uint32_t h1 = ((uint32_t)__bfloat16_as_ushort(hw) << 16) | __bfloat16_as_ushort(hz);
            uint32_t g0 = ((uint32_t)__bfloat16_as_ushort(ly) << 16) | __bfloat16_as_ushort(lx);
            uint32_t g1 = ((uint32_t)__bfloat16_as_ushort(lw) << 16) | __bfloat16_as_ushort(lz);
            const int word = (d0 + 32 * k) * SW + (j0 >> 1);
            *reinterpret_cast<uint2*>(tileH + word) = make_uint2(h0, h1);
            *reinterpret_cast<uint2*>(tileL + word) = make_uint2(g0, g1);
        }
        __syncthreads();

        // ---- prefetch next stage (overlaps mma phase) ----
        if (s + 1 < NST) {
            const float* pg = bg + (s + 1) * JS;
            #pragma unroll
            for (int k = 0; k < 4; ++k)
                R[k] = *reinterpret_cast<const float4*>(pg + (size_t)k * 32 * Tt);
        }

        // ---- mma phase: 4 k-steps of 16 t ----
        #pragma unroll
        for (int q = 0; q < 4; ++q) {
            const int t0q = s * JS + q * 16;
            const int2 Lab01 = *reinterpret_cast<const int2*>(labs + t0q + q2);
            const int2 Lab23 = *reinterpret_cast<const int2*>(labs + t0q + q2 + 8);

            uint32_t A[2][4];
            #pragma unroll
            for (int mi = 0; mi < 2; ++mi) {
                const int r1 = mbase + mi * 16 + rowa;
                const int r2 = r1 + 8;
                A[mi][0] = oh2(Lab01.x, Lab01.y, r1);
                A[mi][1] = oh2(Lab01.x, Lab01.y, r2);
                A[mi][2] = oh2(Lab23.x, Lab23.y, r1);
                A[mi][3] = oh2(Lab23.x, Lab23.y, r2);
            }
            #pragma unroll
            for (int ni = 0; ni < 2; ++ni) {
                const int d = dbase + ni * 8 + rowa;       // n = l>>2
                const int bw = d * SW + q * 8 + (l & 3);
                const uint32_t bh0 = tileH[bw], bh1 = tileH[bw + 4];
                const uint32_t bl0 = tileL[bw], bl1 = tileL[bw + 4];
                #pragma unroll
                for (int mi = 0; mi < 2; ++mi) {
                    mma16816(C[mi][ni], A[mi], bh0, bh1);
                    mma16816(C[mi][ni], A[mi], bl0, bl1);
                }
            }
        }
        __syncthreads();
    }

    // ---- write register C -> per-block partials ----
    {
        float* po = g_partial + (size_t)b * Cc * Dd;
        #pragma unroll
        for (int mi = 0; mi < 2; ++mi) {
            #pragma unroll
            for (int ni = 0; ni < 2; ++ni) {
                const int c = mbase + mi * 16 + rowa;
                const int d = dbase + ni * 8 + q2;
                po[c * Dd + d]           = C[mi][ni][0];
                po[c * Dd + d + 1]       = C[mi][ni][1];
                po[(c + 8) * Dd + d]     = C[mi][ni][2];
                po[(c + 8) * Dd + d + 1] = C[mi][ni][3];
            }
        }
    }
    if (tid < Cc) g_pcnt[tid * G1 + b] = cnt[tid];

    #pragma unroll
    for (int o = 16; o > 0; o >>= 1) sq += __shfl_xor_sync(0xffffffff, sq, o);
    if (l == 0) red[w] = sq;
    __syncthreads();
    if (tid == 0) {
        float s = 0.f;
        #pragma unroll
        for (int i = 0; i < 16; ++i) s += red[i];
        g_psq[b] = s;
    }
}

// ---------------------------------------------------------------------------
// KE: fused epilogue. Block c owns class c: folds count column + 128 partials
// (float4), computes difference + per-class loss term. Block 0 folds sumsq.
// ---------------------------------------------------------------------------
__global__ void kE_finish(const float* __restrict__ centers,
                          float* __restrict__ out) {
    __shared__ float4 sred[256];
    __shared__ float  sS[Dd];
    __shared__ int    scnt;
    __shared__ float  rterm[4];
    __shared__ float  rsq[4];

    const int c = blockIdx.x;
    const int t = threadIdx.x;                     // 256 threads
    const int w = t >> 5, l = t & 31;

    if (t == 0) scnt = 0;
    __syncthreads();

    if (t < G1) {
        int v = g_pcnt[c * G1 + t];
        #pragma unroll
        for (int o = 16; o > 0; o >>= 1) v += __shfl_xor_sync(0xffffffff, v, o);
        if (l == 0) atomicAdd(&scnt, v);
    }
    if (c == 0 && t >= 128) {
        float p = g_psq[t - 128];
        #pragma unroll
        for (int o = 16; o > 0; o >>= 1) p += __shfl_xor_sync(0xffffffff, p, o);
        if (l == 0) rsq[w - 4] = p;
    }

    {
        const float4* gp4 = reinterpret_cast<const float4*>(g_partial);
        const int d4 = t & 31;
        const int sl = t >> 5;
        float4 s = make_float4(0.f, 0.f, 0.f, 0.f);
        #pragma unroll
        for (int g = 0; g < G1 / 8; ++g) {
            float4 v = gp4[(size_t)(sl * (G1 / 8) + g) * 2048 + c * 32 + d4];
            s.x += v.x; s.y += v.y; s.z += v.z; s.w += v.w;
        }
        sred[t] = s;
    }
    __syncthreads();
    if (t < 32) {
        float4 s = sred[t];
        #pragma unroll
        for (int k = 1; k < 8; ++k) {
            float4 v = sred[t + 32 * k];
            s.x += v.x; s.y += v.y; s.z += v.z; s.w += v.w;
        }
        reinterpret_cast<float4*>(sS)[t] = s;
    }
    __syncthreads();

    float term = 0.0f;
    if (t < Dd) {
        const float sv  = sS[t];
        const float fc  = (float)scnt;
        const float ctr = centers[c * Dd + t];
        out[1 + c * Dd + t] = (fc * ctr - sv) / fmaxf(fc, 1.0f);
        term = fc * ctr * ctr - 2.0f * ctr * sv;
    }
    #pragma unroll
    for (int o = 16; o > 0; o >>= 1) term += __shfl_xor_sync(0xffffffff, term, o);
    if (l == 0 && w < 4) rterm[w] = term;
    __syncthreads();
    if (t == 0) {
        g_lpart[c] = rterm[0] + rterm[1] + rterm[2] + rterm[3];
        if (c == 0) g_sumsq = rsq[0] + rsq[1] + rsq[2] + rsq[3];
    }
}

// ---------------------------------------------------------------------------
// K4: final scalar loss
// ---------------------------------------------------------------------------
__global__ void k4_loss(float* __restrict__ out) {
    float ls = 0.f;
    #pragma unroll
    for (int i = 0; i < Cc; ++i) ls += g_lpart[i];
    out[0] = (g_sumsq + ls) / (float)((size_t)NTOT * Dd);
}

// ---------------------------------------------------------------------------
extern "C" void kernel_launch(void* const* d_in, const int* in_sizes, int n_in,
                              void* d_out, int out_size) {
    const float* feature = (const float*)d_in[0];
    const int*   lab32   = (const int*)d_in[1];   // width auto-detected in k1
    const float* centers = (const float*)d_in[2];
    float*       out     = (float*)d_out;

    const int smem_bytes = (2 * TILEW + Tt + Cc + 16 + 1) * 4;
    cudaFuncSetAttribute(k1_main, cudaFuncAttributeMaxDynamicSharedMemorySize,
                         smem_bytes);

    k1_main<<<G1, TH1, smem_bytes>>>(feature, lab32);
    kE_finish<<<Cc, 256>>>(centers, out);
    k4_loss<<<1, 1>>>(out);
}

// round 12
// speedup vs baseline: 1.0258x; 1.0258x over previous
#include <cuda_runtime.h>
#include <cuda_bf16.h>
#include <stdint.h>

// Problem constants
#define Bb 128
#define Dd 128
#define Tt 2048
#define Cc 64
#define NTOT (Bb*Tt)            // 262144 rows

// K1 config: one block per batch row b
#define G1   128
#define TH1  512
#define JS   64                 // t-columns per stage
#define NST  (Tt/JS)            // 32 stages
#define SW   36                 // bf16-tile row stride in 32-bit words (32 data + 4 pad)
#define TILEW (Dd*SW)           // 4608 words per tile
#define AFRW  2048              // A-fragment buffer: 16 sets * 32 lanes * 4 words

// Static device scratch (no allocations allowed)
__device__ float g_partial[(size_t)G1 * Cc * Dd];   // 4 MB per-block partials
__device__ int   g_pcnt[Cc * G1];                   // [c][g]
__device__ float g_psq[G1];
__device__ float g_sumsq;
__device__ float g_lpart[Cc];

// ---------------------------------------------------------------------------
__device__ __forceinline__ uint32_t oh2(int L0, int L1, int r) {
    // packed bf16x2 one-hot: low half = (L0==r), high half = (L1==r)
    return ((L0 == r) ? 0x3F80u : 0u) | ((L1 == r) ? 0x3F800000u : 0u);
}
__device__ __forceinline__ void mma16816(float* c, const uint32_t* a,
                                         uint32_t b0, uint32_t b1) {
    asm volatile(
        "mma.sync.aligned.m16n8k16.row.col.f32.bf16.bf16.f32 "
        "{%0,%1,%2,%3}, {%4,%5,%6,%7}, {%8,%9}, {%0,%1,%2,%3};"
        : "+f"(c[0]), "+f"(c[1]), "+f"(c[2]), "+f"(c[3])
        : "r"(a[0]), "r"(a[1]), "r"(a[2]), "r"(a[3]), "r"(b0), "r"(b1));
}

// ---------------------------------------------------------------------------
// K1: one-hot GEMM via mma.sync (HMMA bf16, hi/lo split), C in registers.
// A-fragments (one-hot, label-only) are computed ONCE per (q,mb,mi) by a
// designated warp into smem and shared by all 16 warps (dedup of the
// dominant ALU cost identified in R10's profile).
// ---------------------------------------------------------------------------
__global__ void __launch_bounds__(TH1, 1)
k1_main(const float* __restrict__ feature, const int* __restrict__ lab32) {
    extern __shared__ float sm[];
    uint32_t* tileH = (uint32_t*)sm;               // 4608 words
    uint32_t* tileL = tileH + TILEW;               // 4608 words
    uint32_t* afrag = tileL + TILEW;               // 2048 words (16-B aligned)
    int*   labs = (int*)(afrag + AFRW);            // 2048 ints
    int*   cnt  = labs + Tt;                       // 64
    float* red  = (float*)(cnt + Cc);              // 16
    int*   sflag= (int*)(red + 16);                // 1

    const int tid = threadIdx.x;
    const int w = tid >> 5;
    const int l = tid & 31;
    const int b = blockIdx.x;

    if (tid < Cc) cnt[tid] = 0;
    if (tid == 0) *sflag = 0;
    __syncthreads();

    // Label-width probe: odd words of the FIRST 4096 int64 slots (word idx
    // < 8192, in-bounds for both widths; values < 64 => genuine int64 buffer
    // has all-zero odd words).
    {
        int any = 0;
        #pragma unroll
        for (int k = 0; k < 4096 / TH1; ++k)
            any |= lab32[(tid + k * TH1) * 2 + 1];
        #pragma unroll
        for (int o = 16; o > 0; o >>= 1) any |= __shfl_xor_sync(0xffffffff, any, o);
        if (l == 0 && any) atomicOr(sflag, 1);
    }
    __syncthreads();
    const int is64 = (*sflag == 0) ? 1 : 0;

    // preload this block's 2048 labels + histogram
    {
        const int base = b * Tt;
        #pragma unroll
        for (int k = 0; k < Tt / TH1; ++k) {
            int i = tid + k * TH1;
            int lab = is64 ? lab32[(base + i) * 2] : lab32[base + i];
            labs[i] = lab;
            atomicAdd(&cnt[lab], 1);
        }
    }
    __syncthreads();

    // ---- mappings ----
    const float* fb = feature + (size_t)b * Dd * Tt;
    const int d0 = tid >> 4;                       // convert: base row 0..31
    const int j0 = (tid & 15) * 4;                 // convert: t offset (float4)
    const float* bg = fb + (size_t)d0 * Tt + j0;

    const int mb   = w & 1;                        // warp's class half (0/1)
    const int dbase = (w >> 1) * 16;               // warp's d range (16 wide)
    const int q2    = (l & 3) * 2;                 // fragment k-pair column
    const int rowa  = l >> 2;                      // fragment row (0..7)

    // A-precompute assignment: warp w owns set (pq, pmb, pmi)
    const int pq  = w >> 2;
    const int pmb = (w >> 1) & 1;
    const int pmi = w & 1;
    const int pr1 = pmb * 32 + pmi * 16 + rowa;
    const int pr2 = pr1 + 8;
    uint4* afrag4 = (uint4*)afrag;                 // 512 uint4 entries

    float C[2][2][4];
    #pragma unroll
    for (int mi = 0; mi < 2; ++mi)
        #pragma unroll
        for (int ni = 0; ni < 2; ++ni)
            #pragma unroll
            for (int q = 0; q < 4; ++q) C[mi][ni][q] = 0.0f;

    float sq = 0.0f;
    float4 R[4];
    #pragma unroll
    for (int k = 0; k < 4; ++k)
        R[k] = *reinterpret_cast<const float4*>(bg + (size_t)k * 32 * Tt);

    for (int s = 0; s < NST; ++s) {
        // ---- convert fp32 -> bf16 hi/lo into tiles (+ sumsq) ----
        #pragma unroll
        for (int k = 0; k < 4; ++k) {
            float4 v = R[k];
            sq += v.x * v.x + v.y * v.y + v.z * v.z + v.w * v.w;
            __nv_bfloat16 hx = __float2bfloat16_rn(v.x), hy = __float2bfloat16_rn(v.y);
            __nv_bfloat16 hz = __float2bfloat16_rn(v.z), hw = __float2bfloat16_rn(v.w);
            __nv_bfloat16 lx = __float2bfloat16_rn(v.x - __bfloat162float(hx));
            __nv_bfloat16 ly = __float2bfloat16_rn(v.y - __bfloat162float(hy));
            __nv_bfloat16 lz = __float2bfloat16_rn(v.z - __bfloat162float(hz));
            __nv_bfloat16 lw = __float2bfloat16_rn(v.w - __bfloat162float(hw));
            uint32_t h0 = ((uint32_t)__bfloat16_as_ushort(hy) << 16) | __bfloat16_as_ushort(hx);
            uint32_t h1 = ((uint32_t)__bfloat16_as_ushort(hw) << 16) | __bfloat16_as_ushort(hz);
            uint32_t g0 = ((uint32_t)__bfloat16_as_ushort(ly) << 16) | __bfloat16_as_ushort(lx);
            uint32_t g1 = ((uint32_t)__bfloat16_as_ushort(lw) << 16) | __bfloat16_as_ushort(lz);
            const int word = (d0 + 32 * k) * SW + (j0 >> 1);
            *reinterpret_cast<uint2*>(tileH + word) = make_uint2(h0, h1);
            *reinterpret_cast<uint2*>(tileL + word) = make_uint2(g0, g1);
        }

        // ---- A-fragment precompute: warp w builds its (pq, pmb, pmi) set ----
        {
            const int t0q = s * JS + pq * 16;
            const int2 L01 = *reinterpret_cast<const int2*>(labs + t0q + q2);
            const int2 L23 = *reinterpret_cast<const int2*>(labs + t0q + q2 + 8);
            uint4 a;
            a.x = oh2(L01.x, L01.y, pr1);
            a.y = oh2(L01.x, L01.y, pr2);
            a.z = oh2(L23.x, L23.y, pr1);
            a.w = oh2(L23.x, L23.y, pr2);
            afrag4[(((pq * 2 + pmb) * 2 + pmi) * 32) + l] = a;
        }
        __syncthreads();

        // ---- prefetch next stage (overlaps mma phase) ----
        if (s + 1 < NST) {
            const float* pg = bg + (s + 1) * JS;
            #pragma unroll
            for (int k = 0; k < 4; ++k)
                R[k] = *reinterpret_cast<const float4*>(pg + (size_t)k * 32 * Tt);
        }

        // ---- mma phase: 4 k-steps of 16 t; A from shared fragments ----
        #pragma unroll
        for (int q = 0; q < 4; ++q) {
            const uint4 Af0 = afrag4[((q * 2 + mb) * 2 + 0) * 32 + l];
            const uint4 Af1 = afrag4[((q * 2 + mb) * 2 + 1) * 32 + l];
            const uint32_t A0[4] = {Af0.x, Af0.y, Af0.z, Af0.w};
            const uint32_t A1[4] = {Af1.x, Af1.y, Af1.z, Af1.w};
            #pragma unroll
            for (int ni = 0; ni < 2; ++ni) {
                const int d = dbase + ni * 8 + rowa;
                const int bw = d * SW + q * 8 + (l & 3);
                const uint32_t bh0 = tileH[bw], bh1 = tileH[bw + 4];
                const uint32_t bl0 = tileL[bw], bl1 = tileL[bw + 4];
                mma16816(C[0][ni], A0, bh0, bh1);
                mma16816(C[1][ni], A1, bh0, bh1);
                mma16816(C[0][ni], A0, bl0, bl1);
                mma16816(C[1][ni], A1, bl0, bl1);
            }
        }
        __syncthreads();
    }

    // ---- write register C -> per-block partials ----
    {
        float* po = g_partial + (size_t)b * Cc * Dd;
        #pragma unroll
        for (int mi = 0; mi < 2; ++mi) {
            #pragma unroll
            for (int ni = 0; ni < 2; ++ni) {
                const int c = mb * 32 + mi * 16 + rowa;
                const int d = dbase + ni * 8 + q2;
                po[c * Dd + d]           = C[mi][ni][0];
                po[c * Dd + d + 1]       = C[mi][ni][1];
                po[(c + 8) * Dd + d]     = C[mi][ni][2];
                po[(c + 8) * Dd + d + 1] = C[mi][ni][3];
            }
        }
    }
    if (tid < Cc) g_pcnt[tid * G1 + b] = cnt[tid];

    #pragma unroll
    for (int o = 16; o > 0; o >>= 1) sq += __shfl_xor_sync(0xffffffff, sq, o);
    if (l == 0) red[w] = sq;
    __syncthreads();
    if (tid == 0) {
        float s = 0.f;
        #pragma unroll
        for (int i = 0; i < 16; ++i) s += red[i];
        g_psq[b] = s;
    }
}

// ---------------------------------------------------------------------------
// KE: fused epilogue. Block c owns class c: folds count column + 128 partials
// (float4), computes difference + per-class loss term. Block 0 folds sumsq.
// ---------------------------------------------------------------------------
__global__ void kE_finish(const float* __restrict__ centers,
                          float* __restrict__ out) {
    __shared__ float4 sred[256];
    __shared__ float  sS[Dd];
    __shared__ int    scnt;
    __shared__ float  rterm[4];
    __shared__ float  rsq[4];

    const int c = blockIdx.x;
    const int t = threadIdx.x;                     // 256 threads
    const int w = t >> 5, l = t & 31;

    if (t == 0) scnt = 0;
    __syncthreads();

    if (t < G1) {
        int v = g_pcnt[c * G1 + t];
        #pragma unroll
        for (int o = 16; o > 0; o >>= 1) v += __shfl_xor_sync(0xffffffff, v, o);
        if (l == 0) atomicAdd(&scnt, v);
    }
    if (c == 0 && t >= 128) {
        float p = g_psq[t - 128];
        #pragma unroll
        for (int o = 16; o > 0; o >>= 1) p += __shfl_xor_sync(0xffffffff, p, o);
        if (l == 0) rsq[w - 4] = p;
    }

    {
        const float4* gp4 = reinterpret_cast<const float4*>(g_partial);
        const int d4 = t & 31;
        const int sl = t >> 5;
        float4 s = make_float4(0.f, 0.f, 0.f, 0.f);
        #pragma unroll
        for (int g = 0; g < G1 / 8; ++g) {
            float4 v = gp4[(size_t)(sl * (G1 / 8) + g) * 2048 + c * 32 + d4];
            s.x += v.x; s.y += v.y; s.z += v.z; s.w += v.w;
        }
        sred[t] = s;
    }
    __syncthreads();
    if (t < 32) {
        float4 s = sred[t];
        #pragma unroll
        for (int k = 1; k < 8; ++k) {
            float4 v = sred[t + 32 * k];
            s.x += v.x; s.y += v.y; s.z += v.z; s.w += v.w;
        }
        reinterpret_cast<float4*>(sS)[t] = s;
    }
    __syncthreads();

    float term = 0.0f;
    if (t < Dd) {
        const float sv  = sS[t];
        const float fc  = (float)scnt;
        const float ctr = centers[c * Dd + t];
        out[1 + c * Dd + t] = (fc * ctr - sv) / fmaxf(fc, 1.0f);
        term = fc * ctr * ctr - 2.0f * ctr * sv;
    }
    #pragma unroll
    for (int o = 16; o > 0; o >>= 1) term += __shfl_xor_sync(0xffffffff, term, o);
    if (l == 0 && w < 4) rterm[w] = term;
    __syncthreads();
    if (t == 0) {
        g_lpart[c] = rterm[0] + rterm[1] + rterm[2] + rterm[3];
        if (c == 0) g_sumsq = rsq[0] + rsq[1] + rsq[2] + rsq[3];
    }
}

// ---------------------------------------------------------------------------
// K4: final scalar loss
// ---------------------------------------------------------------------------
__global__ void k4_loss(float* __restrict__ out) {
    float ls = 0.f;
    #pragma unroll
    for (int i = 0; i < Cc; ++i) ls += g_lpart[i];
    out[0] = (g_sumsq + ls) / (float)((size_t)NTOT * Dd);
}

// ---------------------------------------------------------------------------
extern "C" void kernel_launch(void* const* d_in, const int* in_sizes, int n_in,
                              void* d_out, int out_size) {
    const float* feature = (const float*)d_in[0];
    const int*   lab32   = (const int*)d_in[1];   // width auto-detected in k1
    const float* centers = (const float*)d_in[2];
    float*       out     = (float*)d_out;

    const int smem_bytes = (2 * TILEW + AFRW + Tt + Cc + 16 + 1) * 4;
    cudaFuncSetAttribute(k1_main, cudaFuncAttributeMaxDynamicSharedMemorySize,
                         smem_bytes);

    k1_main<<<G1, TH1, smem_bytes>>>(feature, lab32);
    kE_finish<<<Cc, 256>>>(centers, out);
    k4_loss<<<1, 1>>>(out);
}